// round 16
// baseline (speedup 1.0000x reference)
#include <cuda_runtime.h>
#include <cuda_fp16.h>

#define F_IN 128
#define FS   64
#define NH   8
#define NMAX 4096
#define NBLK 148
#define NTHR 1024
#define XS_ROWS 28               // ceil(NMAX/NBLK)
#define XS_PAD  132              // row stride (floats): 132%32=4 -> rows on distinct banks

// persistent scratch (allocations forbidden)
__device__ __half   g_hh[NMAX][2 * NH];  // node features fp16, PRE-SCALED by 0.5
__device__ double   g_s1, g_s2;          // gate sum / sum of squares
__device__ unsigned g_count = 0;         // grid-barrier arrivals
__device__ unsigned g_gen   = 0;         // grid-barrier generation (monotone)
__device__ unsigned g_done  = 0;         // last-block ticket

__device__ __forceinline__ unsigned h2_to_u(__half2 h) { return *(unsigned*)&h; }
__device__ __forceinline__ __half2 u_to_h2(unsigned u) { return *(__half2*)&u; }
__device__ __forceinline__ __half2 tanh2_fast(__half2 x) {
    unsigned r, xi = h2_to_u(x);
    asm("tanh.approx.f16x2 %0, %1;" : "=r"(r) : "r"(xi));
    return u_to_h2(r);
}

// sense-reversal grid barrier; safe because grid==NBLK<=#SMs (all co-resident)
__device__ __forceinline__ void grid_barrier() {
    __threadfence();
    __syncthreads();
    if (threadIdx.x == 0) {
        unsigned my = *(volatile unsigned*)&g_gen;
        if (atomicAdd(&g_count, 1u) == NBLK - 1) {
            g_count = 0;
            __threadfence();
            atomicAdd(&g_gen, 1u);
        } else {
            while (*(volatile unsigned*)&g_gen == my) { }
            __threadfence();
        }
    }
    __syncthreads();
}

__global__ void __launch_bounds__(NTHR, 1)
fused_kernel(const float* __restrict__ x,
             const float* __restrict__ Wlin,
             const float* __restrict__ blin,
             const float* __restrict__ W1,
             const float* __restrict__ b1,
             const float* __restrict__ W2,
             const float* __restrict__ b2,
             const int*   __restrict__ ei,
             const float* __restrict__ u,
             float* __restrict__ out,
             int N, int E, int out_size) {
    __shared__ float   WlinS[FS][F_IN];     // 32 KB, staged once
    __shared__ float   xS[XS_ROWS][XS_PAD]; // this block's x rows (~14.8 KB)
    __shared__ float   W1x[FS][16];         // W1x[f][t] = W1[t&7][(t<8?0:64)+f]
    __shared__ float   MsP[F_IN][17];       // padded: conflict-free
    __shared__ float   cs[16];
    __shared__ __half2 w2s[NH / 2];
    __shared__ float   b2s;
    __shared__ float   r1[NTHR / 32], r2[NTHR / 32];

    const int tid = threadIdx.x;
    const int epb = (E + NBLK - 1) / NBLK;         // edges per block (<= NTHR)
    const int e0  = blockIdx.x * epb + tid;        // this thread's edge
    const bool ev = (tid < epb) && (e0 < E);

    // ---- issue ALL cold loads up front so their latencies overlap ----
    // (a) stage WlinS: 2048 float4, 2 per thread, coalesced
    {
        const float4* src = (const float4*)Wlin;
        float4* dst = (float4*)&WlinS[0][0];
        dst[tid]        = src[tid];
        dst[tid + 1024] = src[tid + 1024];
    }
    // (b) stage this block's x rows: 896 float4, threads 0-895 (coalesced/row)
    if (tid < XS_ROWS * 32) {
        int row = tid >> 5;                 // 0..27
        int c4  = tid & 31;                 // float4 column
        int node = blockIdx.x + NBLK * row;
        if (node < N)
            *(float4*)&xS[row][c4 * 4] =
                ((const float4*)(x + (size_t)node * F_IN))[c4];
    }
    // (c) stage W1x (transposed+duplicated broadcast layout)
    if (tid < FS * 16) {
        int t = tid & 15, f = tid >> 4;
        W1x[f][t] = W1[(t & 7) * (2 * FS) + ((t < 8) ? 0 : FS) + f];
    }
    // (d) edge prefetch + u-side gate factor
    int   pi = 0, pj = 0;
    float q2 = 0.0f;
    if (ev) {
        pi = ei[e0]; pj = ei[E + e0];
        float uu = u[e0];
        float eps     = fmaf(-0.9998f, uu, 0.9999f);
        float onemeps = fmaf( 0.9998f, uu, 0.0001f);
        float qr = __fdividef(onemeps, eps);
        q2 = qr * qr;
    }
    // (e) tiny constants
    if (tid < NH / 2)
        w2s[tid] = __floats2half2_rn(0.25f * W2[2 * tid], 0.25f * W2[2 * tid + 1]);
    if (tid == 0) {
        float s = 0.0f;
        #pragma unroll
        for (int h = 0; h < NH; h++) s += W2[h];
        b2s = 0.5f * b2[0] + 0.25f * s;
    }
    if (blockIdx.x == 0 && tid == 0) { g_s1 = 0.0; g_s2 = 0.0; }
    __syncthreads();

    // ---- prep: 512 threads x 4 accumulators, all-smem, conflict-free ----
    if (tid < 512) {
        const int k  = tid & 127;
        const int qt = tid >> 7;            // 0..3 -> t in [4qt, 4qt+4)
        float a0 = 0.f, a1 = 0.f, a2 = 0.f, a3 = 0.f;
        #pragma unroll 8
        for (int f = 0; f < FS; f++) {
            float wv = WlinS[f][k];                       // LDS conflict-free
            float4 w1 = *(const float4*)&W1x[f][qt * 4];  // warp-uniform bcast
            a0 = fmaf(wv, w1.x, a0);
            a1 = fmaf(wv, w1.y, a1);
            a2 = fmaf(wv, w1.z, a2);
            a3 = fmaf(wv, w1.w, a3);
        }
        MsP[k][qt * 4 + 0] = a0;
        MsP[k][qt * 4 + 1] = a1;
        MsP[k][qt * 4 + 2] = a2;
        MsP[k][qt * 4 + 3] = a3;
    } else if (tid < 512 + 16) {
        int t = tid - 512;
        float acc = (t < NH) ? b1[t] : 0.0f;
        for (int f = 0; f < FS; f++)
            acc = fmaf(W1x[f][t], __ldg(&blin[f]), acc);
        cs[t] = acc;
    }
    __syncthreads();

    // ---- node features: all-smem now (xS + MsP) ----
    {
        int lg = tid >> 4;                 // 0..63 ; only lg<XS_ROWS can be valid
        int t  = tid & 15;
        int node = blockIdx.x + NBLK * lg;
        bool valid = (lg < XS_ROWS) && (node < N);
        float acc = 0.0f;
        if (valid) {
            const float* xr = &xS[lg][0];
            float b0 = 0.f, b1a = 0.f, b2a = 0.f, b3 = 0.f;
            #pragma unroll
            for (int k4 = 0; k4 < F_IN / 4; k4 += 4) {
                float4 v0 = *(const float4*)&xr[4 * k4 + 0];
                float4 v1 = *(const float4*)&xr[4 * k4 + 4];
                float4 v2 = *(const float4*)&xr[4 * k4 + 8];
                float4 v3 = *(const float4*)&xr[4 * k4 + 12];
                b0 = fmaf(v0.x, MsP[4*k4+ 0][t], b0); b0 = fmaf(v0.y, MsP[4*k4+ 1][t], b0);
                b0 = fmaf(v0.z, MsP[4*k4+ 2][t], b0); b0 = fmaf(v0.w, MsP[4*k4+ 3][t], b0);
                b1a= fmaf(v1.x, MsP[4*k4+ 4][t], b1a);b1a= fmaf(v1.y, MsP[4*k4+ 5][t], b1a);
                b1a= fmaf(v1.z, MsP[4*k4+ 6][t], b1a);b1a= fmaf(v1.w, MsP[4*k4+ 7][t], b1a);
                b2a= fmaf(v2.x, MsP[4*k4+ 8][t], b2a);b2a= fmaf(v2.y, MsP[4*k4+ 9][t], b2a);
                b2a= fmaf(v2.z, MsP[4*k4+10][t], b2a);b2a= fmaf(v2.w, MsP[4*k4+11][t], b2a);
                b3 = fmaf(v3.x, MsP[4*k4+12][t], b3); b3 = fmaf(v3.y, MsP[4*k4+13][t], b3);
                b3 = fmaf(v3.z, MsP[4*k4+14][t], b3); b3 = fmaf(v3.w, MsP[4*k4+15][t], b3);
            }
            acc = 0.5f * (cs[t] + ((b0 + b1a) + (b2a + b3)));   // pre-scale by 0.5
        }
        float accN = __shfl_down_sync(0xffffffffu, acc, 1);
        if (valid && !(t & 1))
            ((__half2*)g_hh[node])[t >> 1] = __floats2half2_rn(acc, accN);
    }
    grid_barrier();   // g_hh complete & visible

    // ---- edges: balanced, <=886 per block ----
    float ls1 = 0.0f, ls2 = 0.0f;
    if (ev) {
        uint4 i_lo = ((const uint4*)g_hh[pi])[0];
        uint4 i_hi = ((const uint4*)g_hh[pi])[1];
        uint4 j_lo = ((const uint4*)g_hh[pj])[0];
        uint4 j_hi = ((const uint4*)g_hh[pj])[1];

        const __half2* il = (const __half2*)&i_lo;
        const __half2* ih = (const __half2*)&i_hi;
        const __half2* jl = (const __half2*)&j_lo;
        const __half2* jh = (const __half2*)&j_hi;

        __half2 aij = __floats2half2_rn(0.0f, 0.0f);
        __half2 aji = aij;
        #pragma unroll
        for (int q = 0; q < 4; q++) {
            aij = __hfma2(w2s[q], tanh2_fast(__hadd2(il[q], jh[q])), aij);
            aji = __hfma2(w2s[q], tanh2_fast(__hadd2(jl[q], ih[q])), aji);
        }
        float2 fij = __half22float2(aij);
        float2 fji = __half22float2(aji);
        __half2 sp = __floats2half2_rn(b2s + fij.x + fij.y, b2s + fji.x + fji.y);
        float2 thf = __half22float2(tanh2_fast(sp));
        float w = fmaf(0.25f, thf.x + thf.y, 0.5f);

        float a = q2 * __expf(-2.0f * w);
        float g = __fdividef(1.0f, 1.0f + a);
        out[e0] = g;
        ls1 = g;
        ls2 = g * g;
    }

    // block reduction of (sum, sumsq)
    #pragma unroll
    for (int o = 16; o > 0; o >>= 1) {
        ls1 += __shfl_down_sync(0xffffffffu, ls1, o);
        ls2 += __shfl_down_sync(0xffffffffu, ls2, o);
    }
    int lane = tid & 31, wid = tid >> 5;
    if (lane == 0) { r1[wid] = ls1; r2[wid] = ls2; }
    __syncthreads();
    if (tid < 32) {
        float a = r1[tid], b = r2[tid];
        #pragma unroll
        for (int o = 16; o > 0; o >>= 1) {
            a += __shfl_down_sync(0xffffffffu, a, o);
            b += __shfl_down_sync(0xffffffffu, b, o);
        }
        if (tid == 0) {
            atomicAdd(&g_s1, (double)a);
            atomicAdd(&g_s2, (double)b);
            __threadfence();
            // last block computes the variance (no second grid barrier)
            if (atomicAdd(&g_done, 1u) == NBLK - 1) {
                g_done = 0;                  // reset for next graph replay
                __threadfence();
                double s1 = atomicAdd(&g_s1, 0.0);
                double s2 = atomicAdd(&g_s2, 0.0);
                double mean = s1 / (double)E;
                out[out_size - 1] = (float)((s2 - s1 * mean) / (double)(E - 1));
            }
        }
    }
}

extern "C" void kernel_launch(void* const* d_in, const int* in_sizes, int n_in,
                              void* d_out, int out_size) {
    const float* x    = (const float*)d_in[0];   // [N, 128]
    const float* Wlin = (const float*)d_in[1];   // [64, 128]
    const float* blin = (const float*)d_in[2];   // [64]
    const float* W1   = (const float*)d_in[3];   // [8, 128]
    const float* b1   = (const float*)d_in[4];   // [8]
    const float* W2   = (const float*)d_in[5];   // [8]
    const float* b2   = (const float*)d_in[6];   // [1]
    const int*   ei   = (const int*)d_in[7];     // [2, E]
    const float* u    = (const float*)d_in[8];   // [E]

    int N = in_sizes[0] / F_IN;
    int E = in_sizes[8];

    fused_kernel<<<NBLK, NTHR>>>(x, Wlin, blin, W1, b1, W2, b2, ei, u,
                                 (float*)d_out, N, E, out_size);
}